// round 4
// baseline (speedup 1.0000x reference)
#include <cuda_runtime.h>
#include <math.h>
#include <stdint.h>

#define BATCH 4
#define SEQ   2048
#define DM    1024
#define DFF   2752
#define NH    16
#define DK    64
#define MROWS (BATCH*SEQ)   /* 8192 */

// ---------------- scratch (static device, no allocs) ----------------
__device__ float g_xn [(size_t)MROWS*DM];   // normed x; later reused as qh
__device__ float g_qkv[(size_t)MROWS*3*DM];
__device__ float g_att[(size_t)MROWS*DM];
__device__ float g_h1 [(size_t)MROWS*DM];
__device__ float g_h  [(size_t)MROWS*DFF]; // ffn h; earlier reused as kh
__device__ float g_g  [(size_t)MROWS*DFF]; // ffn g; earlier reused as vh

// ---------------- RMSNorm (1 block per row, 256 thr = 1024 floats) ----------------
__global__ __launch_bounds__(256) void rmsnorm_k(const float* __restrict__ x,
                                                 const float* __restrict__ gain,
                                                 float* __restrict__ out)
{
    int row = blockIdx.x;
    const float4* xr = (const float4*)(x + (size_t)row * DM);
    float4 v = xr[threadIdx.x];
    float ss = v.x*v.x + v.y*v.y + v.z*v.z + v.w*v.w;
    #pragma unroll
    for (int o = 16; o; o >>= 1) ss += __shfl_xor_sync(0xffffffffu, ss, o);
    __shared__ float red[8];
    __shared__ float rinv;
    if ((threadIdx.x & 31) == 0) red[threadIdx.x >> 5] = ss;
    __syncthreads();
    if (threadIdx.x == 0) {
        float t = 0.f;
        #pragma unroll
        for (int i = 0; i < 8; i++) t += red[i];
        rinv = rsqrtf(t * (1.0f / DM) + 1e-5f);
    }
    __syncthreads();
    float r = rinv;
    float4 g = ((const float4*)gain)[threadIdx.x];
    float4 o4 = make_float4(v.x*g.x*r, v.y*g.y*r, v.z*g.z*r, v.w*g.w*r);
    ((float4*)(out + (size_t)row * DM))[threadIdx.x] = o4;
}

// ---------------- SGEMM: C[M,N] = A[M,K] * B[N,K]^T (+res) ----------------
__global__ __launch_bounds__(256) void sgemm_k(const float* __restrict__ A,
                                               const float* __restrict__ B,
                                               float* __restrict__ C,
                                               const float* __restrict__ res,
                                               int N, int K)
{
    __shared__ float As[2][16][132];
    __shared__ float Bs[2][16][68];

    const int tid = threadIdx.x;
    const int bm = blockIdx.y * 128;
    const int bn = blockIdx.x * 64;
    const int ar = tid >> 2;
    const int ac = (tid & 3) << 2;
    const int ty = tid >> 4;
    const int tx = tid & 15;

    float acc[8][4];
    #pragma unroll
    for (int i = 0; i < 8; i++)
        #pragma unroll
        for (int j = 0; j < 4; j++) acc[i][j] = 0.f;

    const float* Aptr0 = A + (size_t)(bm + ar)      * K + ac;
    const float* Aptr1 = A + (size_t)(bm + ar + 64) * K + ac;
    const float* Bptr  = B + (size_t)(bn + ar)      * K + ac;

    const int nk = K >> 4;

    float4 ra0 = *(const float4*)Aptr0;
    float4 ra1 = *(const float4*)Aptr1;
    float4 rb  = *(const float4*)Bptr;
    {
        As[0][ac+0][ar]    = ra0.x; As[0][ac+1][ar]    = ra0.y;
        As[0][ac+2][ar]    = ra0.z; As[0][ac+3][ar]    = ra0.w;
        As[0][ac+0][ar+64] = ra1.x; As[0][ac+1][ar+64] = ra1.y;
        As[0][ac+2][ar+64] = ra1.z; As[0][ac+3][ar+64] = ra1.w;
        Bs[0][ac+0][ar] = rb.x; Bs[0][ac+1][ar] = rb.y;
        Bs[0][ac+2][ar] = rb.z; Bs[0][ac+3][ar] = rb.w;
    }
    __syncthreads();

    for (int t = 0; t < nk; t++) {
        const int cur = t & 1;
        if (t + 1 < nk) {
            ra0 = *(const float4*)(Aptr0 + (size_t)(t + 1) * 16);
            ra1 = *(const float4*)(Aptr1 + (size_t)(t + 1) * 16);
            rb  = *(const float4*)(Bptr  + (size_t)(t + 1) * 16);
        }
        #pragma unroll
        for (int kk = 0; kk < 16; kk++) {
            float a[8], bb[4];
            *(float4*)&a[0] = *(const float4*)&As[cur][kk][ty * 8];
            *(float4*)&a[4] = *(const float4*)&As[cur][kk][ty * 8 + 4];
            *(float4*)&bb[0] = *(const float4*)&Bs[cur][kk][tx * 4];
            #pragma unroll
            for (int i = 0; i < 8; i++)
                #pragma unroll
                for (int j = 0; j < 4; j++)
                    acc[i][j] += a[i] * bb[j];
        }
        if (t + 1 < nk) {
            const int nxt = cur ^ 1;
            As[nxt][ac+0][ar]    = ra0.x; As[nxt][ac+1][ar]    = ra0.y;
            As[nxt][ac+2][ar]    = ra0.z; As[nxt][ac+3][ar]    = ra0.w;
            As[nxt][ac+0][ar+64] = ra1.x; As[nxt][ac+1][ar+64] = ra1.y;
            As[nxt][ac+2][ar+64] = ra1.z; As[nxt][ac+3][ar+64] = ra1.w;
            Bs[nxt][ac+0][ar] = rb.x; Bs[nxt][ac+1][ar] = rb.y;
            Bs[nxt][ac+2][ar] = rb.z; Bs[nxt][ac+3][ar] = rb.w;
        }
        __syncthreads();
    }

    #pragma unroll
    for (int i = 0; i < 8; i++) {
        const int row = bm + ty * 8 + i;
        const size_t off = (size_t)row * N + bn + tx * 4;
        float4 v = make_float4(acc[i][0], acc[i][1], acc[i][2], acc[i][3]);
        if (res) {
            float4 rv = *(const float4*)(res + off);
            v.x += rv.x; v.y += rv.y; v.z += rv.z; v.w += rv.w;
        }
        *(float4*)(C + off) = v;
    }
}

// ---------------- split qkv + RoPE into head-major Q/K/V ----------------
// One thread per (token m, head h, pair p). Double-precision angle to remove
// any large-argument fp32 trig discrepancy vs the reference.
__global__ __launch_bounds__(256) void qkvsplit_k(const float* __restrict__ qkv,
                                                  float* __restrict__ qh,
                                                  float* __restrict__ kh,
                                                  float* __restrict__ vh)
{
    int idx = blockIdx.x * blockDim.x + threadIdx.x;   // MROWS*NH*32
    if (idx >= MROWS * NH * 32) return;
    int p = idx & 31;
    int h = (idx >> 5) & 15;
    int m = idx >> 9;              // token row 0..8191
    int s = m & (SEQ - 1);         // position within sequence
    int b = m >> 11;               // batch (SEQ = 2048)

    const float* src = qkv + (size_t)m * (3 * DM) + h * DK + 2 * p;
    size_t dst = ((size_t)(b * NH + h) * SEQ + s) * DK + 2 * p;

    // angle = s * 10000^{-2p/64}, computed in double
    double inv = exp(-(double)(2 * p) * (9.210340371976184 / 64.0));
    double sd, cd;
    sincos((double)s * inv, &sd, &cd);
    float c = (float)cd, si = (float)sd;

    float q0 = src[0],        q1 = src[1];
    float k0 = src[DM],       k1 = src[DM + 1];
    float v0 = src[2 * DM],   v1 = src[2 * DM + 1];

    qh[dst] = c * q0 - si * q1;  qh[dst + 1] = si * q0 + c * q1;
    kh[dst] = c * k0 - si * k1;  kh[dst + 1] = si * k0 + c * k1;
    vh[dst] = v0;                vh[dst + 1] = v1;
}

// ---------------- Flash attention v2 (head-major, 1 query/thread) ----------------
#define FBM 128
#define FBN 32
#define NEG_BIG (-1.0e30f)
__global__ __launch_bounds__(128) void flash2_k(const float* __restrict__ qh,
                                                const float* __restrict__ kh,
                                                const float* __restrict__ vh,
                                                float* __restrict__ att)
{
    const int bh = blockIdx.y;              // b*NH + h
    const int b = bh / NH, h = bh % NH;
    const int q = blockIdx.x * FBM + threadIdx.x;   // query position 0..2047

    __shared__ float4 Kt[FBN][16];
    __shared__ float4 Vt[FBN][16];

    const size_t headbase = (size_t)bh * SEQ;
    float4 qr[16], o[16];
    const float4* qp = (const float4*)(qh + (headbase + q) * DK);
    #pragma unroll
    for (int d = 0; d < 16; d++) { qr[d] = qp[d]; o[d] = make_float4(0.f,0.f,0.f,0.f); }

    float mx = NEG_BIG, l = 0.f;
    const int n_end = blockIdx.x * FBM + FBM;

    for (int n0 = 0; n0 < n_end; n0 += FBN) {
        __syncthreads();
        #pragma unroll
        for (int i = 0; i < 4; i++) {
            int f = threadIdx.x + i * 128;   // 512 float4 slots
            int r = f >> 4, c = f & 15;
            Kt[r][c] = ((const float4*)(kh + (headbase + n0 + r) * DK))[c];
            Vt[r][c] = ((const float4*)(vh + (headbase + n0 + r) * DK))[c];
        }
        __syncthreads();

        float sc[FBN];
        #pragma unroll
        for (int j = 0; j < FBN; j++) {
            float acc = 0.f;
            #pragma unroll
            for (int d = 0; d < 16; d++) {
                float4 kv = Kt[j][d];
                acc += qr[d].x*kv.x + qr[d].y*kv.y + qr[d].z*kv.z + qr[d].w*kv.w;
            }
            sc[j] = (n0 + j <= q) ? acc * 0.125f : NEG_BIG;
        }

        float mnew = mx;
        #pragma unroll
        for (int j = 0; j < FBN; j++) mnew = fmaxf(mnew, sc[j]);
        float corr = __expf(mx - mnew);
        float lsum = 0.f;
        #pragma unroll
        for (int j = 0; j < FBN; j++) { float p = __expf(sc[j] - mnew); sc[j] = p; lsum += p; }
        mx = mnew;
        l = l * corr + lsum;
        #pragma unroll
        for (int d = 0; d < 16; d++) { o[d].x *= corr; o[d].y *= corr; o[d].z *= corr; o[d].w *= corr; }
        #pragma unroll
        for (int j = 0; j < FBN; j++) {
            float p = sc[j];
            #pragma unroll
            for (int d = 0; d < 16; d++) {
                float4 v4 = Vt[j][d];
                o[d].x += p * v4.x; o[d].y += p * v4.y;
                o[d].z += p * v4.z; o[d].w += p * v4.w;
            }
        }
    }

    float invl = 1.f / l;
    float4* orow = (float4*)(att + (size_t)(b * SEQ + q) * DM + h * DK);
    #pragma unroll
    for (int d = 0; d < 16; d++)
        orow[d] = make_float4(o[d].x*invl, o[d].y*invl, o[d].z*invl, o[d].w*invl);
}

// ---------------- SiLU(h) * g  ->  h ----------------
__global__ __launch_bounds__(256) void silu_k(float* __restrict__ h,
                                              const float* __restrict__ g,
                                              int n)
{
    int idx = blockIdx.x * blockDim.x + threadIdx.x;
    if (idx >= n) return;
    float hv = h[idx];
    float gv = g[idx];
    h[idx] = gv * hv / (1.f + __expf(-hv));
}

// ---------------- launch ----------------
extern "C" void kernel_launch(void* const* d_in, const int* in_sizes, int n_in,
                              void* d_out, int out_size)
{
    const float* x      = (const float*)d_in[0];
    const float* qkv_w  = (const float*)d_in[2];
    const float* o_w    = (const float*)d_in[3];
    const float* gain1  = (const float*)d_in[4];
    const float* gain2  = (const float*)d_in[5];
    const float* w1     = (const float*)d_in[6];
    const float* w2     = (const float*)d_in[7];
    const float* w3     = (const float*)d_in[8];
    float* out = (float*)d_out;

    float *xn, *qkv, *att, *h1, *hb, *gb;
    cudaGetSymbolAddress((void**)&xn,  g_xn);
    cudaGetSymbolAddress((void**)&qkv, g_qkv);
    cudaGetSymbolAddress((void**)&att, g_att);
    cudaGetSymbolAddress((void**)&h1,  g_h1);
    cudaGetSymbolAddress((void**)&hb,  g_h);
    cudaGetSymbolAddress((void**)&gb,  g_g);

    // scratch aliasing (all uses strictly sequential on one stream):
    // qh reuses g_xn (dead after QKV gemm, until re-filled at step 6)
    // kh reuses g_h, vh reuses g_g (dead until step 7)
    float* qh = xn;
    float* kh = hb;
    float* vh = gb;

    // 1. xn = rmsnorm(x, gain1)
    rmsnorm_k<<<MROWS, 256>>>(x, gain1, xn);
    // 2. qkv = xn @ qkv_w^T   (N=3072, K=1024)
    sgemm_k<<<dim3(3072/64, MROWS/128), 256>>>(xn, qkv_w, qkv, nullptr, 3*DM, DM);
    // 3. split + RoPE -> head-major qh/kh/vh
    {
        int n = MROWS * NH * 32;
        qkvsplit_k<<<(n + 255)/256, 256>>>(qkv, qh, kh, vh);
    }
    // 4. flash attention -> att (token-major, [m][h*64+d])
    flash2_k<<<dim3(SEQ/FBM, BATCH*NH), 128>>>(qh, kh, vh, att);
    // 5. h1 = x + att @ o_w^T
    sgemm_k<<<dim3(DM/64, MROWS/128), 256>>>(att, o_w, h1, x, DM, DM);
    // 6. xn = rmsnorm(h1, gain2)
    rmsnorm_k<<<MROWS, 256>>>(h1, gain2, xn);
    // 7. hb = xn @ w1^T ; gb = xn @ w3^T   (N=2752, K=1024)
    sgemm_k<<<dim3(DFF/64, MROWS/128), 256>>>(xn, w1, hb, nullptr, DFF, DM);
    sgemm_k<<<dim3(DFF/64, MROWS/128), 256>>>(xn, w3, gb, nullptr, DFF, DM);
    // 8. hb = silu(hb) * gb
    {
        int n = MROWS * DFF;
        silu_k<<<(n + 255)/256, 256>>>(hb, gb, n);
    }
    // 9. out = h1 + hb @ w2^T  (K=2752)
    sgemm_k<<<dim3(DM/64, MROWS/128), 256>>>(hb, w2, out, h1, DM, DFF);
}

// round 6
// speedup vs baseline: 1.5842x; 1.5842x over previous
#include <cuda_runtime.h>
#include <cuda_bf16.h>
#include <math.h>
#include <stdint.h>

#define BATCH 4
#define SEQ   2048
#define DM    1024
#define DFF   2752
#define DFP   2816   /* DFF padded to multiple of 128 */
#define NH    16
#define DK    64
#define MROWS (BATCH*SEQ)   /* 8192 */

// ================= scratch (static device, no allocs) =================
__device__ float g_qkv[(size_t)MROWS*3*DM];
__device__ float g_att[(size_t)MROWS*DM];
__device__ float g_h1 [(size_t)MROWS*DM];
__device__ float g_xn [(size_t)MROWS*DM];    // qh
__device__ float g_h  [(size_t)MROWS*DFP];   // hb / kh
__device__ float g_g  [(size_t)MROWS*DFP];   // gb / vh
__device__ __nv_bfloat16 g_ah[(size_t)MROWS*DFP];
__device__ __nv_bfloat16 g_al[(size_t)MROWS*DFP];
#define NWELEM 12845056
__device__ __nv_bfloat16 g_wh[(size_t)NWELEM];
__device__ __nv_bfloat16 g_wl[(size_t)NWELEM];
// weight arena offsets (elements)
#define OQKV 0          /* 3072x1024  */
#define OO   3145728    /* 1024x1024  */
#define OW1  4194304    /* 2816x1024  */
#define OW3  7077888    /* 2816x1024  */
#define OW2  9961472    /* 1024x2816  */

// ================= PTX helpers (sm_100 baseline features) =================
__device__ __forceinline__ uint32_t smem_u32(const void* p) {
    uint32_t a;
    asm("{ .reg .u64 t; cvta.to.shared.u64 t, %1; cvt.u32.u64 %0, t; }" : "=r"(a) : "l"(p));
    return a;
}
__device__ __forceinline__ void cpa16(uint32_t s, const void* g) {
    asm volatile("cp.async.cg.shared.global [%0], [%1], 16;" :: "r"(s), "l"(g));
}
#define CP_COMMIT() asm volatile("cp.async.commit_group;" ::: "memory")
#define CP_WAIT1()  asm volatile("cp.async.wait_group 1;" ::: "memory")

__device__ __forceinline__ void ldm_x4(uint32_t* r, uint32_t a) {
    asm volatile("ldmatrix.sync.aligned.m8n8.x4.shared.b16 {%0,%1,%2,%3}, [%4];"
                 : "=r"(r[0]), "=r"(r[1]), "=r"(r[2]), "=r"(r[3]) : "r"(a));
}
__device__ __forceinline__ void ldm_x2(uint32_t* r, uint32_t a) {
    asm volatile("ldmatrix.sync.aligned.m8n8.x2.shared.b16 {%0,%1}, [%2];"
                 : "=r"(r[0]), "=r"(r[1]) : "r"(a));
}
#define MMA(d, a, b) \
    asm volatile("mma.sync.aligned.m16n8k16.row.col.f32.bf16.bf16.f32 " \
        "{%0,%1,%2,%3}, {%4,%5,%6,%7}, {%8,%9}, {%0,%1,%2,%3};" \
        : "+f"((d)[0]), "+f"((d)[1]), "+f"((d)[2]), "+f"((d)[3]) \
        : "r"((a)[0]), "r"((a)[1]), "r"((a)[2]), "r"((a)[3]), "r"((b)[0]), "r"((b)[1]))

// ================= bf16 split helpers =================
__device__ __forceinline__ void split1(float x, __nv_bfloat16& h, __nv_bfloat16& l) {
    h = __float2bfloat16(x);
    l = __float2bfloat16(x - __bfloat162float(h));
}

// plain fp32 -> (hi,lo) split over n4 float4 groups
__global__ __launch_bounds__(256) void split_k(const float* __restrict__ src,
                                               __nv_bfloat16* __restrict__ hi,
                                               __nv_bfloat16* __restrict__ lo,
                                               int n4)
{
    int i = blockIdx.x * 256 + threadIdx.x;
    if (i >= n4) return;
    float4 v = ((const float4*)src)[i];
    __nv_bfloat16 h0,h1,h2,h3,l0,l1,l2,l3;
    split1(v.x,h0,l0); split1(v.y,h1,l1); split1(v.z,h2,l2); split1(v.w,h3,l3);
    ((__nv_bfloat162*)hi)[i*2]   = __nv_bfloat162(h0,h1);
    ((__nv_bfloat162*)hi)[i*2+1] = __nv_bfloat162(h2,h3);
    ((__nv_bfloat162*)lo)[i*2]   = __nv_bfloat162(l0,l1);
    ((__nv_bfloat162*)lo)[i*2+1] = __nv_bfloat162(l2,l3);
}

// split with 2D zero padding: src[srows][scols] -> dst[drows][dcols]
__global__ __launch_bounds__(256) void split_pad_k(const float* __restrict__ src,
                                                   __nv_bfloat16* __restrict__ hi,
                                                   __nv_bfloat16* __restrict__ lo,
                                                   int srows, int scols,
                                                   int drows, int dcols)
{
    int i = blockIdx.x * 256 + threadIdx.x;
    int n4 = drows * (dcols >> 2);
    if (i >= n4) return;
    int r  = i / (dcols >> 2);
    int c4 = (i - r * (dcols >> 2)) << 2;
    float4 v = make_float4(0.f, 0.f, 0.f, 0.f);
    if (r < srows && c4 < scols)
        v = *(const float4*)(src + (size_t)r * scols + c4);
    __nv_bfloat16 h0,h1,h2,h3,l0,l1,l2,l3;
    split1(v.x,h0,l0); split1(v.y,h1,l1); split1(v.z,h2,l2); split1(v.w,h3,l3);
    size_t o = (size_t)r * dcols + c4;
    ((__nv_bfloat162*)(hi + o))[0] = __nv_bfloat162(h0,h1);
    ((__nv_bfloat162*)(hi + o))[1] = __nv_bfloat162(h2,h3);
    ((__nv_bfloat162*)(lo + o))[0] = __nv_bfloat162(l0,l1);
    ((__nv_bfloat162*)(lo + o))[1] = __nv_bfloat162(l2,l3);
}

// ================= RMSNorm -> split bf16 hi/lo =================
__global__ __launch_bounds__(256) void rmsnorm_split_k(const float* __restrict__ x,
                                                       const float* __restrict__ gain,
                                                       __nv_bfloat16* __restrict__ hi,
                                                       __nv_bfloat16* __restrict__ lo)
{
    int row = blockIdx.x;
    const float4* xr = (const float4*)(x + (size_t)row * DM);
    float4 v = xr[threadIdx.x];
    float ss = v.x*v.x + v.y*v.y + v.z*v.z + v.w*v.w;
    #pragma unroll
    for (int o = 16; o; o >>= 1) ss += __shfl_xor_sync(0xffffffffu, ss, o);
    __shared__ float red[8];
    __shared__ float rinv;
    if ((threadIdx.x & 31) == 0) red[threadIdx.x >> 5] = ss;
    __syncthreads();
    if (threadIdx.x == 0) {
        float t = 0.f;
        #pragma unroll
        for (int i = 0; i < 8; i++) t += red[i];
        rinv = rsqrtf(t * (1.0f / DM) + 1e-5f);
    }
    __syncthreads();
    float r = rinv;
    float4 g = ((const float4*)gain)[threadIdx.x];
    float y0 = v.x*g.x*r, y1 = v.y*g.y*r, y2 = v.z*g.z*r, y3 = v.w*g.w*r;
    __nv_bfloat16 h0,h1,h2,h3,l0,l1,l2,l3;
    split1(y0,h0,l0); split1(y1,h1,l1); split1(y2,h2,l2); split1(y3,h3,l3);
    size_t base = (size_t)row * (DM/2) + threadIdx.x * 2;
    ((__nv_bfloat162*)hi)[base]   = __nv_bfloat162(h0,h1);
    ((__nv_bfloat162*)hi)[base+1] = __nv_bfloat162(h2,h3);
    ((__nv_bfloat162*)lo)[base]   = __nv_bfloat162(l0,l1);
    ((__nv_bfloat162*)lo)[base+1] = __nv_bfloat162(l2,l3);
}

// ================= SiLU(h)*g -> split bf16 hi/lo =================
__global__ __launch_bounds__(256) void silu_split_k(const float* __restrict__ h,
                                                    const float* __restrict__ g,
                                                    __nv_bfloat16* __restrict__ hi,
                                                    __nv_bfloat16* __restrict__ lo,
                                                    int n4)
{
    int i = blockIdx.x * 256 + threadIdx.x;
    if (i >= n4) return;
    float4 hv = ((const float4*)h)[i];
    float4 gv = ((const float4*)g)[i];
    float y0 = gv.x * hv.x / (1.f + __expf(-hv.x));
    float y1 = gv.y * hv.y / (1.f + __expf(-hv.y));
    float y2 = gv.z * hv.z / (1.f + __expf(-hv.z));
    float y3 = gv.w * hv.w / (1.f + __expf(-hv.w));
    __nv_bfloat16 h0,h1,h2,h3,l0,l1,l2,l3;
    split1(y0,h0,l0); split1(y1,h1,l1); split1(y2,h2,l2); split1(y3,h3,l3);
    ((__nv_bfloat162*)hi)[i*2]   = __nv_bfloat162(h0,h1);
    ((__nv_bfloat162*)hi)[i*2+1] = __nv_bfloat162(h2,h3);
    ((__nv_bfloat162*)lo)[i*2]   = __nv_bfloat162(l0,l1);
    ((__nv_bfloat162*)lo)[i*2+1] = __nv_bfloat162(l2,l3);
}

// ================= HMMA bf16x3 GEMM =================
// C[M,N] = (Ah+Al)[M,K] x (Bh+Bl)[N,K]^T (+res), fp32 out.
// 128x128x32 CTA tile, 256 threads, 8 warps (2x4), 64x32 per warp.
#define GBK 32
#define LDT 40                 /* smem row stride in bf16 (32 + 8 pad) */
#define TBUF (128*LDT)         /* bf16 per (buf,part) tile = 5120 */
#define SMEMB (8 * TBUF * 2)   /* 81920 bytes: A:4 tiles, B:4 tiles */

__global__ __launch_bounds__(256) void gemmh_k(
    const __nv_bfloat16* __restrict__ Ah, const __nv_bfloat16* __restrict__ Al,
    const __nv_bfloat16* __restrict__ Bh, const __nv_bfloat16* __restrict__ Bl,
    float* __restrict__ C, const float* __restrict__ res, int N, int K)
{
    extern __shared__ __align__(128) __nv_bfloat16 sm[];
    const uint32_t smb = smem_u32(sm);
    const int tid  = threadIdx.x;
    const int lane = tid & 31;
    const int wid  = tid >> 5;
    const int wm   = wid >> 2;          // 0..1  (64 rows each)
    const int wn   = wid & 3;           // 0..3  (32 cols each)
    const int bm   = blockIdx.y * 128;
    const int bn   = blockIdx.x * 128;

    float acc[4][4][4];
    #pragma unroll
    for (int a = 0; a < 4; a++)
        #pragma unroll
        for (int b = 0; b < 4; b++)
            #pragma unroll
            for (int c = 0; c < 4; c++) acc[a][b][c] = 0.f;

    // smem offsets (bf16 units): A hi/lo for buf: (buf*2+part)*TBUF ; B: +4*TBUF
    const int row = tid >> 2;               // 0..63  (loader, chunk row half 1)
    const int kc  = (tid & 3) << 3;         // 0,8,16,24 (bf16)

    #define LOAD_STAGE(s, buf) do {                                            \
        int k0_ = (s) * GBK;                                                   \
        _Pragma("unroll")                                                      \
        for (int i_ = 0; i_ < 2; i_++) {                                       \
            int r_ = row + i_ * 64;                                            \
            size_t ga_ = (size_t)(bm + r_) * K + k0_ + kc;                     \
            size_t gb_ = (size_t)(bn + r_) * K + k0_ + kc;                     \
            uint32_t sa_ = smb + (uint32_t)(((buf)*2)*TBUF + r_*LDT + kc)*2;   \
            uint32_t sb_ = sa_ + (uint32_t)(4*TBUF)*2;                         \
            cpa16(sa_,            Ah + ga_);                                   \
            cpa16(sa_ + TBUF*2,   Al + ga_);                                   \
            cpa16(sb_,            Bh + gb_);                                   \
            cpa16(sb_ + TBUF*2,   Bl + gb_);                                   \
        }                                                                      \
        CP_COMMIT();                                                           \
    } while (0)

    const int NS = K / GBK;
    LOAD_STAGE(0, 0);
    LOAD_STAGE(1, 1);

    // ldmatrix lane address components
    const int arow = lane & 15;                    // row within 16 (x4 quad layout)
    const int acолd = 0;
    (void)acолd;
    const int acolo = ((lane >> 4) << 3);          // 0 or 8
    const int bro  = lane & 7;                     // B row within 8
    const int bcolo = (((lane >> 3) & 1) << 3);    // 0 or 8 (lanes 0-15 used)

    for (int s = 0; s < NS; s++) {
        const int buf = s & 1;
        CP_WAIT1();
        __syncthreads();

        const uint32_t aoff = smb + (uint32_t)((buf*2)*TBUF)*2;
        const uint32_t boff = smb + (uint32_t)((4 + buf*2)*TBUF)*2;

        #pragma unroll
        for (int ks = 0; ks < 2; ks++) {
            const int k0 = ks * 16;
            uint32_t aH[4][4], aL[4][4], bH[4][2], bL[4][2];
            #pragma unroll
            for (int mt = 0; mt < 4; mt++) {
                int r = wm * 64 + mt * 16 + arow;
                uint32_t ad = aoff + (uint32_t)(r * LDT + k0 + acolo) * 2;
                ldm_x4(aH[mt], ad);
                ldm_x4(aL[mt], ad + TBUF*2);
            }
            #pragma unroll
            for (int nt = 0; nt < 4; nt++) {
                int n = wn * 32 + nt * 8 + bro;
                uint32_t bd = boff + (uint32_t)(n * LDT + k0 + bcolo) * 2;
                ldm_x2(bH[nt], bd);
                ldm_x2(bL[nt], bd + TBUF*2);
            }
            #pragma unroll
            for (int mt = 0; mt < 4; mt++)
                #pragma unroll
                for (int nt = 0; nt < 4; nt++) {
                    MMA(acc[mt][nt], aH[mt], bH[nt]);
                    MMA(acc[mt][nt], aH[mt], bL[nt]);
                    MMA(acc[mt][nt], aL[mt], bH[nt]);
                }
        }
        __syncthreads();
        if (s + 2 < NS) LOAD_STAGE(s + 2, buf);
    }

    // epilogue
    const int gid = lane >> 2, t4 = lane & 3;
    #pragma unroll
    for (int mt = 0; mt < 4; mt++) {
        int r0 = bm + wm * 64 + mt * 16 + gid;
        #pragma unroll
        for (int nt = 0; nt < 4; nt++) {
            int col = bn + wn * 32 + nt * 8 + t4 * 2;
            size_t o0 = (size_t)r0 * N + col;
            size_t o1 = o0 + (size_t)8 * N;
            float2 v0 = make_float2(acc[mt][nt][0], acc[mt][nt][1]);
            float2 v1 = make_float2(acc[mt][nt][2], acc[mt][nt][3]);
            if (res) {
                float2 r0v = *(const float2*)(res + o0);
                float2 r1v = *(const float2*)(res + o1);
                v0.x += r0v.x; v0.y += r0v.y;
                v1.x += r1v.x; v1.y += r1v.y;
            }
            *(float2*)(C + o0) = v0;
            *(float2*)(C + o1) = v1;
        }
    }
}

// ================= split qkv + RoPE into head-major Q/K/V =================
__global__ __launch_bounds__(256) void qkvsplit_k(const float* __restrict__ qkv,
                                                  float* __restrict__ qh,
                                                  float* __restrict__ kh,
                                                  float* __restrict__ vh)
{
    int idx = blockIdx.x * blockDim.x + threadIdx.x;
    if (idx >= MROWS * NH * 32) return;
    int p = idx & 31;
    int h = (idx >> 5) & 15;
    int m = idx >> 9;
    int s = m & (SEQ - 1);
    int b = m >> 11;

    const float* src = qkv + (size_t)m * (3 * DM) + h * DK + 2 * p;
    size_t dst = ((size_t)(b * NH + h) * SEQ + s) * DK + 2 * p;

    double inv = exp(-(double)(2 * p) * (9.210340371976184 / 64.0));
    double sd, cd;
    sincos((double)s * inv, &sd, &cd);
    float c = (float)cd, si = (float)sd;

    float q0 = src[0],      q1 = src[1];
    float k0 = src[DM],     k1 = src[DM + 1];
    float v0 = src[2*DM],   v1 = src[2*DM + 1];

    qh[dst] = c*q0 - si*q1;  qh[dst+1] = si*q0 + c*q1;
    kh[dst] = c*k0 - si*k1;  kh[dst+1] = si*k0 + c*k1;
    vh[dst] = v0;            vh[dst+1] = v1;
}

// ================= Flash attention (fp32, head-major) =================
#define FBM 128
#define FBN 32
#define NEG_BIG (-1.0e30f)
__global__ __launch_bounds__(128) void flash2_k(const float* __restrict__ qh,
                                                const float* __restrict__ kh,
                                                const float* __restrict__ vh,
                                                float* __restrict__ att)
{
    const int bh = blockIdx.y;
    const int b = bh / NH, h = bh % NH;
    const int q = blockIdx.x * FBM + threadIdx.x;

    __shared__ float4 Kt[FBN][16];
    __shared__ float4 Vt[FBN][16];

    const size_t headbase = (size_t)bh * SEQ;
    float4 qr[16], o[16];
    const float4* qp = (const float4*)(qh + (headbase + q) * DK);
    #pragma unroll
    for (int d = 0; d < 16; d++) { qr[d] = qp[d]; o[d] = make_float4(0.f,0.f,0.f,0.f); }

    float mx = NEG_BIG, l = 0.f;
    const int n_end = blockIdx.x * FBM + FBM;

    for (int n0 = 0; n0 < n_end; n0 += FBN) {
        __syncthreads();
        #pragma unroll
        for (int i = 0; i < 4; i++) {
            int f = threadIdx.x + i * 128;
            int r = f >> 4, c = f & 15;
            Kt[r][c] = ((const float4*)(kh + (headbase + n0 + r) * DK))[c];
            Vt[r][c] = ((const float4*)(vh + (headbase + n0 + r) * DK))[c];
        }
        __syncthreads();

        float sc[FBN];
        #pragma unroll
        for (int j = 0; j < FBN; j++) {
            float acc = 0.f;
            #pragma unroll
            for (int d = 0; d < 16; d++) {
                float4 kv = Kt[j][d];
                acc += qr[d].x*kv.x + qr[d].y*kv.y + qr[d].z*kv.z + qr[d].w*kv.w;
            }
            sc[j] = (n0 + j <= q) ? acc * 0.125f : NEG_BIG;
        }

        float mnew = mx;
        #pragma unroll
        for (int j = 0; j < FBN; j++) mnew = fmaxf(mnew, sc[j]);
        float corr = __expf(mx - mnew);
        float lsum = 0.f;
        #pragma unroll
        for (int j = 0; j < FBN; j++) { float p = __expf(sc[j] - mnew); sc[j] = p; lsum += p; }
        mx = mnew;
        l = l * corr + lsum;
        #pragma unroll
        for (int d = 0; d < 16; d++) { o[d].x *= corr; o[d].y *= corr; o[d].z *= corr; o[d].w *= corr; }
        #pragma unroll
        for (int j = 0; j < FBN; j++) {
            float p = sc[j];
            #pragma unroll
            for (int d = 0; d < 16; d++) {
                float4 v4 = Vt[j][d];
                o[d].x += p*v4.x; o[d].y += p*v4.y; o[d].z += p*v4.z; o[d].w += p*v4.w;
            }
        }
    }

    float invl = 1.f / l;
    float4* orow = (float4*)(att + (size_t)(b * SEQ + q) * DM + h * DK);
    #pragma unroll
    for (int d = 0; d < 16; d++)
        orow[d] = make_float4(o[d].x*invl, o[d].y*invl, o[d].z*invl, o[d].w*invl);
}

// ================= launch =================
extern "C" void kernel_launch(void* const* d_in, const int* in_sizes, int n_in,
                              void* d_out, int out_size)
{
    const float* x      = (const float*)d_in[0];
    const float* qkv_w  = (const float*)d_in[2];
    const float* o_w    = (const float*)d_in[3];
    const float* gain1  = (const float*)d_in[4];
    const float* gain2  = (const float*)d_in[5];
    const float* w1     = (const float*)d_in[6];
    const float* w2     = (const float*)d_in[7];
    const float* w3     = (const float*)d_in[8];
    float* out = (float*)d_out;

    float *qkv, *att, *h1, *qh, *hb, *gb;
    __nv_bfloat16 *ah, *al, *wh, *wl;
    cudaGetSymbolAddress((void**)&qkv, g_qkv);
    cudaGetSymbolAddress((void**)&att, g_att);
    cudaGetSymbolAddress((void**)&h1,  g_h1);
    cudaGetSymbolAddress((void**)&qh,  g_xn);
    cudaGetSymbolAddress((void**)&hb,  g_h);
    cudaGetSymbolAddress((void**)&gb,  g_g);
    cudaGetSymbolAddress((void**)&ah,  g_ah);
    cudaGetSymbolAddress((void**)&al,  g_al);
    cudaGetSymbolAddress((void**)&wh,  g_wh);
    cudaGetSymbolAddress((void**)&wl,  g_wl);

    float* kh = hb;   // aliases, strictly sequential usage
    float* vh = gb;

    cudaFuncSetAttribute(gemmh_k, cudaFuncAttributeMaxDynamicSharedMemorySize, SMEMB);

    // 0. split weights fp32 -> bf16 hi/lo (with zero padding where needed)
    split_pad_k<<<(3145728/4 + 255)/256, 256>>>(qkv_w, wh+OQKV, wl+OQKV, 3072, 1024, 3072, 1024);
    split_pad_k<<<(1048576/4 + 255)/256, 256>>>(o_w,   wh+OO,   wl+OO,   1024, 1024, 1024, 1024);
    split_pad_k<<<((DFP*1024)/4 + 255)/256, 256>>>(w1, wh+OW1,  wl+OW1,  DFF, 1024, DFP, 1024);
    split_pad_k<<<((DFP*1024)/4 + 255)/256, 256>>>(w3, wh+OW3,  wl+OW3,  DFF, 1024, DFP, 1024);
    split_pad_k<<<((1024*DFP)/4 + 255)/256, 256>>>(w2, wh+OW2,  wl+OW2,  1024, DFF, 1024, DFP);

    // 1. rmsnorm(x) -> ah/al  [8192,1024]
    rmsnorm_split_k<<<MROWS, 256>>>(x, gain1, ah, al);
    // 2. qkv = xn @ qkv_w^T   (N=3072, K=1024)
    gemmh_k<<<dim3(3072/128, MROWS/128), 256, SMEMB>>>(ah, al, wh+OQKV, wl+OQKV, qkv, nullptr, 3*DM, DM);
    // 3. split + RoPE
    qkvsplit_k<<<(MROWS*NH*32 + 255)/256, 256>>>(qkv, qh, kh, vh);
    // 4. flash attention
    flash2_k<<<dim3(SEQ/FBM, BATCH*NH), 128>>>(qh, kh, vh, att);
    // 5. split att, h1 = x + att @ o_w^T  (N=1024, K=1024)
    split_k<<<((MROWS*DM)/4 + 255)/256, 256>>>(att, ah, al, (MROWS*DM)/4);
    gemmh_k<<<dim3(DM/128, MROWS/128), 256, SMEMB>>>(ah, al, wh+OO, wl+OO, h1, x, DM, DM);
    // 6. rmsnorm(h1) -> ah/al
    rmsnorm_split_k<<<MROWS, 256>>>(h1, gain2, ah, al);
    // 7. hb = xn @ w1^T ; gb = xn @ w3^T   (N=2816 padded, K=1024)
    gemmh_k<<<dim3(DFP/128, MROWS/128), 256, SMEMB>>>(ah, al, wh+OW1, wl+OW1, hb, nullptr, DFP, DM);
    gemmh_k<<<dim3(DFP/128, MROWS/128), 256, SMEMB>>>(ah, al, wh+OW3, wl+OW3, gb, nullptr, DFP, DM);
    // 8. silu(hb)*gb -> ah/al  [8192,2816] (pad cols are zero)
    silu_split_k<<<((MROWS*DFP)/4 + 255)/256, 256>>>(hb, gb, ah, al, (MROWS*DFP)/4);
    // 9. out = h1 + (silu prod) @ w2^T  (N=1024, K=2816)
    gemmh_k<<<dim3(DM/128, MROWS/128), 256, SMEMB>>>(ah, al, wh+OW2, wl+OW2, out, h1, DM, DFP);
}

// round 7
// speedup vs baseline: 3.0014x; 1.8946x over previous
#include <cuda_runtime.h>
#include <cuda_bf16.h>
#include <math.h>
#include <stdint.h>

#define BATCH 4
#define SEQ   2048
#define DM    1024
#define DFF   2752
#define DFP   2816   /* DFF padded to multiple of 128 */
#define NH    16
#define DK    64
#define MROWS (BATCH*SEQ)   /* 8192 */

// ================= scratch (static device, no allocs) =================
__device__ float g_qkv[(size_t)MROWS*3*DM];
__device__ float g_att[(size_t)MROWS*DM];
__device__ float g_h1 [(size_t)MROWS*DM];
__device__ float g_xn [(size_t)MROWS*DM];    // holds qhb+khb (bf16) during attention
__device__ float g_h  [(size_t)MROWS*DFP];   // vhb (bf16) then hb fp32
__device__ float g_g  [(size_t)MROWS*DFP];   // gb
__device__ float g_rt [SEQ*32*2];            // rope cos/sin table
__device__ __nv_bfloat16 g_ah[(size_t)MROWS*DFP];
__device__ __nv_bfloat16 g_al[(size_t)MROWS*DFP];
#define NWELEM 12845056
__device__ __nv_bfloat16 g_wh[(size_t)NWELEM];
__device__ __nv_bfloat16 g_wl[(size_t)NWELEM];
#define OQKV 0
#define OO   3145728
#define OW1  4194304
#define OW3  7077888
#define OW2  9961472

// ================= PTX helpers (sm_100 baseline) =================
__device__ __forceinline__ uint32_t smem_u32(const void* p) {
    uint32_t a;
    asm("{ .reg .u64 t; cvta.to.shared.u64 t, %1; cvt.u32.u64 %0, t; }" : "=r"(a) : "l"(p));
    return a;
}
__device__ __forceinline__ void cpa16(uint32_t s, const void* g) {
    asm volatile("cp.async.cg.shared.global [%0], [%1], 16;" :: "r"(s), "l"(g));
}
#define CP_COMMIT() asm volatile("cp.async.commit_group;" ::: "memory")
#define CP_WAIT1()  asm volatile("cp.async.wait_group 1;" ::: "memory")
#define CP_WAIT0()  asm volatile("cp.async.wait_group 0;" ::: "memory")

__device__ __forceinline__ void ldm_x4(uint32_t* r, uint32_t a) {
    asm volatile("ldmatrix.sync.aligned.m8n8.x4.shared.b16 {%0,%1,%2,%3}, [%4];"
                 : "=r"(r[0]), "=r"(r[1]), "=r"(r[2]), "=r"(r[3]) : "r"(a));
}
__device__ __forceinline__ void ldm_x2(uint32_t* r, uint32_t a) {
    asm volatile("ldmatrix.sync.aligned.m8n8.x2.shared.b16 {%0,%1}, [%2];"
                 : "=r"(r[0]), "=r"(r[1]) : "r"(a));
}
__device__ __forceinline__ void ldm_x2t(uint32_t* r, uint32_t a) {
    asm volatile("ldmatrix.sync.aligned.m8n8.x2.trans.shared.b16 {%0,%1}, [%2];"
                 : "=r"(r[0]), "=r"(r[1]) : "r"(a));
}
#define MMA(d, a, b) \
    asm volatile("mma.sync.aligned.m16n8k16.row.col.f32.bf16.bf16.f32 " \
        "{%0,%1,%2,%3}, {%4,%5,%6,%7}, {%8,%9}, {%0,%1,%2,%3};" \
        : "+f"((d)[0]), "+f"((d)[1]), "+f"((d)[2]), "+f"((d)[3]) \
        : "r"((a)[0]), "r"((a)[1]), "r"((a)[2]), "r"((a)[3]), "r"((b)[0]), "r"((b)[1]))

__device__ __forceinline__ uint32_t packbf(float a, float b) {
    __nv_bfloat162 t = __floats2bfloat162_rn(a, b);
    return *(uint32_t*)&t;
}
__device__ __forceinline__ void split1(float x, __nv_bfloat16& h, __nv_bfloat16& l) {
    h = __float2bfloat16(x);
    l = __float2bfloat16(x - __bfloat162float(h));
}

// ================= rope table =================
__global__ __launch_bounds__(256) void ropetab_k(float* __restrict__ rt)
{
    int idx = blockIdx.x * 256 + threadIdx.x;   // SEQ*32
    if (idx >= SEQ * 32) return;
    int s = idx >> 5, p = idx & 31;
    double inv = exp(-(double)(2 * p) * (9.210340371976184 / 64.0));
    double sd, cd;
    sincos((double)s * inv, &sd, &cd);
    rt[idx * 2]     = (float)cd;
    rt[idx * 2 + 1] = (float)sd;
}

// ================= weight split (zero-padded) =================
__global__ __launch_bounds__(256) void split_pad_k(const float* __restrict__ src,
                                                   __nv_bfloat16* __restrict__ hi,
                                                   __nv_bfloat16* __restrict__ lo,
                                                   int srows, int scols,
                                                   int drows, int dcols)
{
    int i = blockIdx.x * 256 + threadIdx.x;
    int n4 = drows * (dcols >> 2);
    if (i >= n4) return;
    int r  = i / (dcols >> 2);
    int c4 = (i - r * (dcols >> 2)) << 2;
    float4 v = make_float4(0.f, 0.f, 0.f, 0.f);
    if (r < srows && c4 < scols)
        v = *(const float4*)(src + (size_t)r * scols + c4);
    __nv_bfloat16 h0,h1,h2,h3,l0,l1,l2,l3;
    split1(v.x,h0,l0); split1(v.y,h1,l1); split1(v.z,h2,l2); split1(v.w,h3,l3);
    size_t o = (size_t)r * dcols + c4;
    ((__nv_bfloat162*)(hi + o))[0] = __nv_bfloat162(h0,h1);
    ((__nv_bfloat162*)(hi + o))[1] = __nv_bfloat162(h2,h3);
    ((__nv_bfloat162*)(lo + o))[0] = __nv_bfloat162(l0,l1);
    ((__nv_bfloat162*)(lo + o))[1] = __nv_bfloat162(l2,l3);
}

// ================= RMSNorm -> split bf16 hi/lo =================
__global__ __launch_bounds__(256) void rmsnorm_split_k(const float* __restrict__ x,
                                                       const float* __restrict__ gain,
                                                       __nv_bfloat16* __restrict__ hi,
                                                       __nv_bfloat16* __restrict__ lo)
{
    int row = blockIdx.x;
    const float4* xr = (const float4*)(x + (size_t)row * DM);
    float4 v = xr[threadIdx.x];
    float ss = v.x*v.x + v.y*v.y + v.z*v.z + v.w*v.w;
    #pragma unroll
    for (int o = 16; o; o >>= 1) ss += __shfl_xor_sync(0xffffffffu, ss, o);
    __shared__ float red[8];
    __shared__ float rinv;
    if ((threadIdx.x & 31) == 0) red[threadIdx.x >> 5] = ss;
    __syncthreads();
    if (threadIdx.x == 0) {
        float t = 0.f;
        #pragma unroll
        for (int i = 0; i < 8; i++) t += red[i];
        rinv = rsqrtf(t * (1.0f / DM) + 1e-5f);
    }
    __syncthreads();
    float r = rinv;
    float4 g = ((const float4*)gain)[threadIdx.x];
    float y0 = v.x*g.x*r, y1 = v.y*g.y*r, y2 = v.z*g.z*r, y3 = v.w*g.w*r;
    __nv_bfloat16 h0,h1,h2,h3,l0,l1,l2,l3;
    split1(y0,h0,l0); split1(y1,h1,l1); split1(y2,h2,l2); split1(y3,h3,l3);
    size_t base = (size_t)row * (DM/2) + threadIdx.x * 2;
    ((__nv_bfloat162*)hi)[base]   = __nv_bfloat162(h0,h1);
    ((__nv_bfloat162*)hi)[base+1] = __nv_bfloat162(h2,h3);
    ((__nv_bfloat162*)lo)[base]   = __nv_bfloat162(l0,l1);
    ((__nv_bfloat162*)lo)[base+1] = __nv_bfloat162(l2,l3);
}

// ================= SiLU(h)*g -> split bf16 hi/lo =================
__global__ __launch_bounds__(256) void silu_split_k(const float* __restrict__ h,
                                                    const float* __restrict__ g,
                                                    __nv_bfloat16* __restrict__ hi,
                                                    __nv_bfloat16* __restrict__ lo,
                                                    int n4)
{
    int i = blockIdx.x * 256 + threadIdx.x;
    if (i >= n4) return;
    float4 hv = ((const float4*)h)[i];
    float4 gv = ((const float4*)g)[i];
    float y0 = gv.x * hv.x / (1.f + __expf(-hv.x));
    float y1 = gv.y * hv.y / (1.f + __expf(-hv.y));
    float y2 = gv.z * hv.z / (1.f + __expf(-hv.z));
    float y3 = gv.w * hv.w / (1.f + __expf(-hv.w));
    __nv_bfloat16 h0,h1,h2,h3,l0,l1,l2,l3;
    split1(y0,h0,l0); split1(y1,h1,l1); split1(y2,h2,l2); split1(y3,h3,l3);
    ((__nv_bfloat162*)hi)[i*2]   = __nv_bfloat162(h0,h1);
    ((__nv_bfloat162*)hi)[i*2+1] = __nv_bfloat162(h2,h3);
    ((__nv_bfloat162*)lo)[i*2]   = __nv_bfloat162(l0,l1);
    ((__nv_bfloat162*)lo)[i*2+1] = __nv_bfloat162(l2,l3);
}

// ================= HMMA bf16x3 GEMM (unchanged, verified) =================
#define GBK 32
#define LDT 40
#define TBUF (128*LDT)
#define SMEMB (8 * TBUF * 2)

__global__ __launch_bounds__(256) void gemmh_k(
    const __nv_bfloat16* __restrict__ Ah, const __nv_bfloat16* __restrict__ Al,
    const __nv_bfloat16* __restrict__ Bh, const __nv_bfloat16* __restrict__ Bl,
    float* __restrict__ C, const float* __restrict__ res, int N, int K)
{
    extern __shared__ __align__(128) __nv_bfloat16 sm[];
    const uint32_t smb = smem_u32(sm);
    const int tid  = threadIdx.x;
    const int lane = tid & 31;
    const int wid  = tid >> 5;
    const int wm   = wid >> 2;
    const int wn   = wid & 3;
    const int bm   = blockIdx.y * 128;
    const int bn   = blockIdx.x * 128;

    float acc[4][4][4];
    #pragma unroll
    for (int a = 0; a < 4; a++)
        #pragma unroll
        for (int b = 0; b < 4; b++)
            #pragma unroll
            for (int c = 0; c < 4; c++) acc[a][b][c] = 0.f;

    const int row = tid >> 2;
    const int kc  = (tid & 3) << 3;

    #define LOAD_STAGE(s, buf) do {                                            \
        int k0_ = (s) * GBK;                                                   \
        _Pragma("unroll")                                                      \
        for (int i_ = 0; i_ < 2; i_++) {                                       \
            int r_ = row + i_ * 64;                                            \
            size_t ga_ = (size_t)(bm + r_) * K + k0_ + kc;                     \
            size_t gb_ = (size_t)(bn + r_) * K + k0_ + kc;                     \
            uint32_t sa_ = smb + (uint32_t)(((buf)*2)*TBUF + r_*LDT + kc)*2;   \
            uint32_t sb_ = sa_ + (uint32_t)(4*TBUF)*2;                         \
            cpa16(sa_,            Ah + ga_);                                   \
            cpa16(sa_ + TBUF*2,   Al + ga_);                                   \
            cpa16(sb_,            Bh + gb_);                                   \
            cpa16(sb_ + TBUF*2,   Bl + gb_);                                   \
        }                                                                      \
        CP_COMMIT();                                                           \
    } while (0)

    const int NS = K / GBK;
    LOAD_STAGE(0, 0);
    LOAD_STAGE(1, 1);

    const int arow = lane & 15;
    const int acolo = ((lane >> 4) << 3);
    const int bro  = lane & 7;
    const int bcolo = (((lane >> 3) & 1) << 3);

    for (int s = 0; s < NS; s++) {
        const int buf = s & 1;
        CP_WAIT1();
        __syncthreads();

        const uint32_t aoff = smb + (uint32_t)((buf*2)*TBUF)*2;
        const uint32_t boff = smb + (uint32_t)((4 + buf*2)*TBUF)*2;

        #pragma unroll
        for (int ks = 0; ks < 2; ks++) {
            const int k0 = ks * 16;
            uint32_t aH[4][4], aL[4][4], bH[4][2], bL[4][2];
            #pragma unroll
            for (int mt = 0; mt < 4; mt++) {
                int r = wm * 64 + mt * 16 + arow;
                uint32_t ad = aoff + (uint32_t)(r * LDT + k0 + acolo) * 2;
                ldm_x4(aH[mt], ad);
                ldm_x4(aL[mt], ad + TBUF*2);
            }
            #pragma unroll
            for (int nt = 0; nt < 4; nt++) {
                int n = wn * 32 + nt * 8 + bro;
                uint32_t bd = boff + (uint32_t)(n * LDT + k0 + bcolo) * 2;
                ldm_x2(bH[nt], bd);
                ldm_x2(bL[nt], bd + TBUF*2);
            }
            #pragma unroll
            for (int mt = 0; mt < 4; mt++)
                #pragma unroll
                for (int nt = 0; nt < 4; nt++) {
                    MMA(acc[mt][nt], aH[mt], bH[nt]);
                    MMA(acc[mt][nt], aH[mt], bL[nt]);
                    MMA(acc[mt][nt], aL[mt], bH[nt]);
                }
        }
        __syncthreads();
        if (s + 2 < NS) LOAD_STAGE(s + 2, buf);
    }

    const int gid = lane >> 2, t4 = lane & 3;
    #pragma unroll
    for (int mt = 0; mt < 4; mt++) {
        int r0 = bm + wm * 64 + mt * 16 + gid;
        #pragma unroll
        for (int nt = 0; nt < 4; nt++) {
            int col = bn + wn * 32 + nt * 8 + t4 * 2;
            size_t o0 = (size_t)r0 * N + col;
            size_t o1 = o0 + (size_t)8 * N;
            float2 v0 = make_float2(acc[mt][nt][0], acc[mt][nt][1]);
            float2 v1 = make_float2(acc[mt][nt][2], acc[mt][nt][3]);
            if (res) {
                float2 r0v = *(const float2*)(res + o0);
                float2 r1v = *(const float2*)(res + o1);
                v0.x += r0v.x; v0.y += r0v.y;
                v1.x += r1v.x; v1.y += r1v.y;
            }
            *(float2*)(C + o0) = v0;
            *(float2*)(C + o1) = v1;
        }
    }
}

// ================= qkv split + RoPE -> bf16 head-major =================
__global__ __launch_bounds__(256) void qkvsplit_bf_k(const float* __restrict__ qkv,
                                                     const float* __restrict__ rt,
                                                     __nv_bfloat16* __restrict__ qhb,
                                                     __nv_bfloat16* __restrict__ khb,
                                                     __nv_bfloat16* __restrict__ vhb)
{
    int idx = blockIdx.x * blockDim.x + threadIdx.x;   // MROWS*NH*32
    if (idx >= MROWS * NH * 32) return;
    int p = idx & 31;
    int h = (idx >> 5) & 15;
    int m = idx >> 9;
    int s = m & (SEQ - 1);
    int b = m >> 11;

    const float* src = qkv + (size_t)m * (3 * DM) + h * DK + 2 * p;
    size_t dst = ((size_t)(b * NH + h) * SEQ + s) * DK + 2 * p;

    float2 cs = ((const float2*)rt)[s * 32 + p];
    float c = cs.x, si = cs.y;

    float q0 = src[0],      q1 = src[1];
    float k0 = src[DM],     k1 = src[DM + 1];
    float v0 = src[2*DM],   v1 = src[2*DM + 1];

    *(__nv_bfloat162*)(qhb + dst) = __floats2bfloat162_rn(c*q0 - si*q1, si*q0 + c*q1);
    *(__nv_bfloat162*)(khb + dst) = __floats2bfloat162_rn(c*k0 - si*k1, si*k0 + c*k1);
    *(__nv_bfloat162*)(vhb + dst) = __floats2bfloat162_rn(v0, v1);
}

// ================= HMMA flash attention =================
// 64 q-rows per block, 4 warps (16 rows each). bf16 QK^T and PV via m16n8k16.
// Writes output split (hi/lo bf16) directly for the o-proj GEMM.
#define QT 64
#define LDS 72
#define NEG_BIG (-1.0e30f)

__global__ __launch_bounds__(128) void flashm_k(const __nv_bfloat16* __restrict__ qhb,
                                                const __nv_bfloat16* __restrict__ khb,
                                                const __nv_bfloat16* __restrict__ vhb,
                                                __nv_bfloat16* __restrict__ ah,
                                                __nv_bfloat16* __restrict__ al)
{
    __shared__ __align__(128) __nv_bfloat16 Qs[QT * LDS];
    __shared__ __align__(128) __nv_bfloat16 Ks[2][64 * LDS];
    __shared__ __align__(128) __nv_bfloat16 Vs[2][64 * LDS];

    const int tid  = threadIdx.x;
    const int lane = tid & 31;
    const int w    = tid >> 5;
    const int bh   = blockIdx.y;            // b*NH + h
    const int b    = bh >> 4, h = bh & 15;
    const int qt   = gridDim.x - 1 - blockIdx.x;   // heavy blocks first
    const int qbase = qt * QT;

    const uint32_t qs = smem_u32(Qs);
    const uint32_t ks0 = smem_u32(Ks);
    const uint32_t vs0 = smem_u32(Vs);

    // load Q tile (64 x 64 bf16)
    const __nv_bfloat16* qg = qhb + ((size_t)bh * SEQ + qbase) * DK;
    #pragma unroll
    for (int i = 0; i < 4; i++) {
        int slot = tid + (i << 7);
        int r = slot >> 3, c8 = (slot & 7) << 3;
        cpa16(qs + (uint32_t)(r * LDS + c8) * 2, qg + r * 64 + c8);
    }
    CP_COMMIT();

    const __nv_bfloat16* kg = khb + (size_t)bh * SEQ * DK;
    const __nv_bfloat16* vg = vhb + (size_t)bh * SEQ * DK;

    #define FKV_LOAD(t, buf) do {                                              \
        int n0_ = (t) * 64;                                                    \
        _Pragma("unroll")                                                      \
        for (int i_ = 0; i_ < 4; i_++) {                                       \
            int slot_ = tid + (i_ << 7);                                       \
            int r_ = slot_ >> 3, c8_ = (slot_ & 7) << 3;                       \
            uint32_t so_ = (uint32_t)((buf) * 64 * LDS + r_ * LDS + c8_) * 2;  \
            cpa16(ks0 + so_, kg + (size_t)(n0_ + r_) * 64 + c8_);              \
            cpa16(vs0 + so_, vg + (size_t)(n0_ + r_) * 64 + c8_);              \
        }                                                                      \
        CP_COMMIT();                                                           \
    } while (0)

    const int T = qt + 1;
    FKV_LOAD(0, 0);

    const int gid = lane >> 2, t4 = lane & 3;
    const int qg0 = qbase + w * 16 + gid;     // this thread's row (and +8)

    uint32_t aQ[4][4];
    float oacc[8][4];
    #pragma unroll
    for (int i = 0; i < 8; i++)
        #pragma unroll
        for (int j = 0; j < 4; j++) oacc[i][j] = 0.f;
    float m0 = NEG_BIG, m1 = NEG_BIG, l0 = 0.f, l1 = 0.f;

    const int arow = lane & 15;
    const int acolo = (lane >> 4) << 3;
    const int bro = lane & 7;
    const int bcolo = ((lane >> 3) & 1) << 3;
    const int l15 = lane & 15;

    for (int t = 0; t < T; t++) {
        const int buf = t & 1;
        if (t + 1 < T) { FKV_LOAD(t + 1, buf ^ 1); CP_WAIT1(); }
        else           { CP_WAIT0(); }
        __syncthreads();

        if (t == 0) {   // Q frags (Q smem now valid)
            #pragma unroll
            for (int k = 0; k < 4; k++) {
                uint32_t ad = qs + (uint32_t)((w * 16 + arow) * LDS + k * 16 + acolo) * 2;
                ldm_x4(aQ[k], ad);
            }
        }

        const uint32_t kb = ks0 + (uint32_t)(buf * 64 * LDS) * 2;
        const uint32_t vb = vs0 + (uint32_t)(buf * 64 * LDS) * 2;
        const int n0 = t * 64;

        // ---- scores S = Q K^T ----
        float sacc[8][4];
        #pragma unroll
        for (int i = 0; i < 8; i++)
            #pragma unroll
            for (int j = 0; j < 4; j++) sacc[i][j] = 0.f;

        #pragma unroll
        for (int k = 0; k < 4; k++) {
            #pragma unroll
            for (int nt = 0; nt < 8; nt++) {
                uint32_t bk[2];
                uint32_t bd = kb + (uint32_t)((nt * 8 + bro) * LDS + k * 16 + bcolo) * 2;
                ldm_x2(bk, bd);
                MMA(sacc[nt], aQ[k], bk);
            }
        }

        // ---- scale + mask ----
        const bool diag = (t == qt);
        #pragma unroll
        for (int nt = 0; nt < 8; nt++) {
            int kvb = n0 + nt * 8 + t4 * 2;
            #pragma unroll
            for (int c = 0; c < 2; c++) {
                float s0 = sacc[nt][c]   * 0.125f;
                float s1 = sacc[nt][c+2] * 0.125f;
                if (diag) {
                    if (kvb + c > qg0)     s0 = NEG_BIG;
                    if (kvb + c > qg0 + 8) s1 = NEG_BIG;
                }
                sacc[nt][c]   = s0;
                sacc[nt][c+2] = s1;
            }
        }

        // ---- online softmax ----
        float vmax0 = NEG_BIG, vmax1 = NEG_BIG;
        #pragma unroll
        for (int nt = 0; nt < 8; nt++) {
            vmax0 = fmaxf(vmax0, fmaxf(sacc[nt][0], sacc[nt][1]));
            vmax1 = fmaxf(vmax1, fmaxf(sacc[nt][2], sacc[nt][3]));
        }
        vmax0 = fmaxf(vmax0, __shfl_xor_sync(0xffffffffu, vmax0, 1));
        vmax0 = fmaxf(vmax0, __shfl_xor_sync(0xffffffffu, vmax0, 2));
        vmax1 = fmaxf(vmax1, __shfl_xor_sync(0xffffffffu, vmax1, 1));
        vmax1 = fmaxf(vmax1, __shfl_xor_sync(0xffffffffu, vmax1, 2));

        float mn0 = fmaxf(m0, vmax0), mn1 = fmaxf(m1, vmax1);
        float corr0 = __expf(m0 - mn0), corr1 = __expf(m1 - mn1);
        m0 = mn0; m1 = mn1;

        float lsum0 = 0.f, lsum1 = 0.f;
        #pragma unroll
        for (int nt = 0; nt < 8; nt++) {
            float p0 = __expf(sacc[nt][0] - mn0);
            float p1 = __expf(sacc[nt][1] - mn0);
            float p2 = __expf(sacc[nt][2] - mn1);
            float p3 = __expf(sacc[nt][3] - mn1);
            sacc[nt][0] = p0; sacc[nt][1] = p1; sacc[nt][2] = p2; sacc[nt][3] = p3;
            lsum0 += p0 + p1; lsum1 += p2 + p3;
        }
        lsum0 += __shfl_xor_sync(0xffffffffu, lsum0, 1);
        lsum0 += __shfl_xor_sync(0xffffffffu, lsum0, 2);
        lsum1 += __shfl_xor_sync(0xffffffffu, lsum1, 1);
        lsum1 += __shfl_xor_sync(0xffffffffu, lsum1, 2);
        l0 = l0 * corr0 + lsum0;
        l1 = l1 * corr1 + lsum1;

        #pragma unroll
        for (int nt = 0; nt < 8; nt++) {
            oacc[nt][0] *= corr0; oacc[nt][1] *= corr0;
            oacc[nt][2] *= corr1; oacc[nt][3] *= corr1;
        }

        // ---- O += P V ----
        #pragma unroll
        for (int kp = 0; kp < 4; kp++) {
            uint32_t pa[4];
            pa[0] = packbf(sacc[2*kp][0],   sacc[2*kp][1]);
            pa[1] = packbf(sacc[2*kp][2],   sacc[2*kp][3]);
            pa[2] = packbf(sacc[2*kp+1][0], sacc[2*kp+1][1]);
            pa[3] = packbf(sacc[2*kp+1][2], sacc[2*kp+1][3]);
            #pragma unroll
            for (int ntd = 0; ntd < 8; ntd++) {
                uint32_t bv[2];
                uint32_t vd = vb + (uint32_t)((kp * 16 + l15) * LDS + ntd * 8) * 2;
                ldm_x2t(bv, vd);
                MMA(oacc[ntd], pa, bv);
            }
        }
        __syncthreads();
    }

    // ---- epilogue: normalize and write hi/lo split ----
    float invl0 = 1.f / l0, invl1 = 1.f / l1;
    const size_t row0 = (size_t)(b * SEQ + qbase + w * 16 + gid);
    #pragma unroll
    for (int ntd = 0; ntd < 8; ntd++) {
        int col = h * 64 + ntd * 8 + t4 * 2;
        float a0 = oacc[ntd][0] * invl0, a1 = oacc[ntd][1] * invl0;
        float b0 = oacc[ntd][2] * invl1, b1 = oacc[ntd][3] * invl1;
        __nv_bfloat16 h0,h1,h2,h3,L0,L1,L2,L3;
        split1(a0,h0,L0); split1(a1,h1,L1); split1(b0,h2,L2); split1(b1,h3,L3);
        *(__nv_bfloat162*)(ah + row0 * DM + col)       = __nv_bfloat162(h0,h1);
        *(__nv_bfloat162*)(al + row0 * DM + col)       = __nv_bfloat162(L0,L1);
        *(__nv_bfloat162*)(ah + (row0 + 8) * DM + col) = __nv_bfloat162(h2,h3);
        *(__nv_bfloat162*)(al + (row0 + 8) * DM + col) = __nv_bfloat162(L2,L3);
    }
}

// ================= launch =================
extern "C" void kernel_launch(void* const* d_in, const int* in_sizes, int n_in,
                              void* d_out, int out_size)
{
    const float* x      = (const float*)d_in[0];
    const float* qkv_w  = (const float*)d_in[2];
    const float* o_w    = (const float*)d_in[3];
    const float* gain1  = (const float*)d_in[4];
    const float* gain2  = (const float*)d_in[5];
    const float* w1     = (const float*)d_in[6];
    const float* w2     = (const float*)d_in[7];
    const float* w3     = (const float*)d_in[8];
    float* out = (float*)d_out;

    float *qkv, *h1, *hb, *gb, *rt, *xn;
    __nv_bfloat16 *ah, *al, *wh, *wl;
    cudaGetSymbolAddress((void**)&qkv, g_qkv);
    cudaGetSymbolAddress((void**)&h1,  g_h1);
    cudaGetSymbolAddress((void**)&xn,  g_xn);
    cudaGetSymbolAddress((void**)&hb,  g_h);
    cudaGetSymbolAddress((void**)&gb,  g_g);
    cudaGetSymbolAddress((void**)&rt,  g_rt);
    cudaGetSymbolAddress((void**)&ah,  g_ah);
    cudaGetSymbolAddress((void**)&al,  g_al);
    cudaGetSymbolAddress((void**)&wh,  g_wh);
    cudaGetSymbolAddress((void**)&wl,  g_wl);

    // bf16 aliases for attention inputs
    __nv_bfloat16* qhb = (__nv_bfloat16*)xn;                      // 16.8MB
    __nv_bfloat16* khb = (__nv_bfloat16*)xn + (size_t)MROWS*DM;   // 16.8MB
    __nv_bfloat16* vhb = (__nv_bfloat16*)hb;                      // reused before FFN

    cudaFuncSetAttribute(gemmh_k, cudaFuncAttributeMaxDynamicSharedMemorySize, SMEMB);

    // launches ordered so ncu -s 5 captures the QKV GEMM
    ropetab_k<<<(SEQ*32 + 255)/256, 256>>>(rt);                                            // 0
    split_pad_k<<<(3145728/4 + 255)/256, 256>>>(qkv_w, wh+OQKV, wl+OQKV, 3072,1024,3072,1024); // 1
    split_pad_k<<<(1048576/4 + 255)/256, 256>>>(o_w,   wh+OO,   wl+OO,   1024,1024,1024,1024); // 2
    split_pad_k<<<((DFP*1024)/4 + 255)/256, 256>>>(w1, wh+OW1, wl+OW1, DFF,1024,DFP,1024);     // 3
    rmsnorm_split_k<<<MROWS, 256>>>(x, gain1, ah, al);                                     // 4
    gemmh_k<<<dim3(3072/128, MROWS/128), 256, SMEMB>>>(ah, al, wh+OQKV, wl+OQKV, qkv, nullptr, 3*DM, DM); // 5
    qkvsplit_bf_k<<<(MROWS*NH*32 + 255)/256, 256>>>(qkv, rt, qhb, khb, vhb);               // 6
    flashm_k<<<dim3(SEQ/QT, BATCH*NH), 128>>>(qhb, khb, vhb, ah, al);                      // 7
    gemmh_k<<<dim3(DM/128, MROWS/128), 256, SMEMB>>>(ah, al, wh+OO, wl+OO, h1, x, DM, DM); // 8
    rmsnorm_split_k<<<MROWS, 256>>>(h1, gain2, ah, al);                                    // 9
    split_pad_k<<<((DFP*1024)/4 + 255)/256, 256>>>(w3, wh+OW3, wl+OW3, DFF,1024,DFP,1024); // 10
    gemmh_k<<<dim3(DFP/128, MROWS/128), 256, SMEMB>>>(ah, al, wh+OW1, wl+OW1, hb, nullptr, DFP, DM); // 11
    gemmh_k<<<dim3(DFP/128, MROWS/128), 256, SMEMB>>>(ah, al, wh+OW3, wl+OW3, gb, nullptr, DFP, DM); // 12
    split_pad_k<<<((1024*DFP)/4 + 255)/256, 256>>>(w2, wh+OW2, wl+OW2, 1024,DFF,1024,DFP); // 13
    silu_split_k<<<((MROWS*DFP)/4 + 255)/256, 256>>>(hb, gb, ah, al, (MROWS*DFP)/4);       // 14
    gemmh_k<<<dim3(DM/128, MROWS/128), 256, SMEMB>>>(ah, al, wh+OW2, wl+OW2, out, h1, DM, DFP); // 15
}